// round 5
// baseline (speedup 1.0000x reference)
#include <cuda_runtime.h>
#include <cstdint>

#define B_ 512
#define T_ 2048
#define S_ 128
#define P_ 1985
#define THREADS 512
#define BSTRIDE 68   // f32 stride for shapelet rows: conflict-free frag loads

// smem float layout: xr[2176] | Bs[128*68] | p2c[2048] | s2[128] | wmin[256]
#define SMEM_FLOATS (2176 + 128 * BSTRIDE + 2048 + 128 + 256)
#define SMEM_BYTES  (SMEM_FLOATS * 4)

extern __shared__ float smf[];

static __device__ __forceinline__ float tf32r(float v) {
    float r;
    asm("cvt.rna.tf32.f32 %0, %1;" : "=f"(r) : "f"(v));
    return r;
}

static __device__ __forceinline__ void mma8_zc(float d[4],
        uint32_t a0, uint32_t a1, uint32_t a2, uint32_t a3,
        uint32_t b0, uint32_t b1) {
    asm volatile(
        "mma.sync.aligned.m16n8k8.row.col.f32.tf32.tf32.f32 "
        "{%0,%1,%2,%3}, {%4,%5,%6,%7}, {%8,%9}, {%10,%10,%10,%10};"
        : "=f"(d[0]), "=f"(d[1]), "=f"(d[2]), "=f"(d[3])
        : "r"(a0), "r"(a1), "r"(a2), "r"(a3), "r"(b0), "r"(b1), "f"(0.f));
}
static __device__ __forceinline__ void mma8_acc(float d[4],
        uint32_t a0, uint32_t a1, uint32_t a2, uint32_t a3,
        uint32_t b0, uint32_t b1) {
    asm volatile(
        "mma.sync.aligned.m16n8k8.row.col.f32.tf32.tf32.f32 "
        "{%0,%1,%2,%3}, {%4,%5,%6,%7}, {%8,%9}, {%0,%1,%2,%3};"
        : "+f"(d[0]), "+f"(d[1]), "+f"(d[2]), "+f"(d[3])
        : "r"(a0), "r"(a1), "r"(a2), "r"(a3), "r"(b0), "r"(b1));
}

// One m-group: prefetch next group's A-words + p2c, then 16 MMAs as 4
// interleaved independent chains (nc0/nc1 x k-lo/k-hi), then min-fold.
static __device__ __forceinline__ void mg_step(
        const uint32_t v[18], uint32_t nxt[18],
        int av_next, int rb_next,
        const uint32_t Bf[2][8][2],
        float pc0, float pc1, float& npc0, float& npc1,
        float mn[4],
        const uint32_t* __restrict__ xu, const float* __restrict__ p2c) {
    // ---- prefetch (overlaps with MMA latency) ----
#pragma unroll
    for (int j = 0; j < 18; ++j) nxt[j] = xu[av_next + 4 * j];
    npc0 = p2c[rb_next];
    npc1 = p2c[rb_next + 8];

    // ---- 4 independent chains, round-robin issue ----
    float A0[4], A1[4], B0[4], B1[4];
    mma8_zc(A0, v[0], v[2], v[1], v[3], Bf[0][0][0], Bf[0][0][1]);
    mma8_zc(A1, v[0], v[2], v[1], v[3], Bf[1][0][0], Bf[1][0][1]);
    mma8_zc(B0, v[8], v[10], v[9], v[11], Bf[0][4][0], Bf[0][4][1]);
    mma8_zc(B1, v[8], v[10], v[9], v[11], Bf[1][4][0], Bf[1][4][1]);
#pragma unroll
    for (int kc = 1; kc < 4; ++kc) {
        const int kh = kc + 4;
        mma8_acc(A0, v[2 * kc], v[2 * kc + 2], v[2 * kc + 1], v[2 * kc + 3],
                 Bf[0][kc][0], Bf[0][kc][1]);
        mma8_acc(A1, v[2 * kc], v[2 * kc + 2], v[2 * kc + 1], v[2 * kc + 3],
                 Bf[1][kc][0], Bf[1][kc][1]);
        mma8_acc(B0, v[2 * kh], v[2 * kh + 2], v[2 * kh + 1], v[2 * kh + 3],
                 Bf[0][kh][0], Bf[0][kh][1]);
        mma8_acc(B1, v[2 * kh], v[2 * kh + 2], v[2 * kh + 1], v[2 * kh + 3],
                 Bf[1][kh][0], Bf[1][kh][1]);
    }
    // ---- combine halves + min-fold (fma/alu pipes, off critical path) ----
    mn[0] = fminf(mn[0], fminf(fmaf(A0[0] + B0[0], -2.f, pc0),
                               fmaf(A0[2] + B0[2], -2.f, pc1)));
    mn[1] = fminf(mn[1], fminf(fmaf(A0[1] + B0[1], -2.f, pc0),
                               fmaf(A0[3] + B0[3], -2.f, pc1)));
    mn[2] = fminf(mn[2], fminf(fmaf(A1[0] + B1[0], -2.f, pc0),
                               fmaf(A1[2] + B1[2], -2.f, pc1)));
    mn[3] = fminf(mn[3], fminf(fmaf(A1[1] + B1[1], -2.f, pc0),
                               fmaf(A1[3] + B1[3], -2.f, pc1)));
}

__global__ void __launch_bounds__(THREADS, 1)
shapelet_mma_kernel(const float* __restrict__ x,
                    const float* __restrict__ sh,
                    float* __restrict__ out) {
    float* xr   = smf;                       // x row, tf32-rounded, padded to 2176
    float* Bs   = smf + 2176;                // centered shapelets (tf32), [128][68]
    float* p2c  = Bs + 128 * BSTRIDE;        // centered window sq-norm, 2048
    float* s2   = p2c + 2048;                // RAW shapelet sq-norm, 128
    float* wmin = s2 + 128;                  // per-half per-col mins, 2*128

    const int tid = threadIdx.x, b = blockIdx.x;
    const int wid = tid >> 5, lane = tid & 31;
    const int gid = lane >> 2, tig = lane & 3;

    // ---- x row (tf32-rounded so MMA and stats agree) ----
    const float* xg = x + (size_t)b * T_;
    for (int i = tid; i < 2176; i += THREADS)
        xr[i] = (i < T_) ? tf32r(xg[i]) : 0.f;

    // ---- centered shapelets (tf32) ; s2 = RAW squared norm ----
    if (tid < S_) {
        const float* sp = sh + tid * 64;
        float sm = 0.f, q2raw = 0.f;
#pragma unroll
        for (int l = 0; l < 64; ++l) {
            float v = sp[l];
            sm += v;
            q2raw = fmaf(v, v, q2raw);
        }
        float mean = sm * (1.f / 64.f);
#pragma unroll
        for (int l = 0; l < 64; ++l)
            Bs[tid * BSTRIDE + l] = tf32r(sp[l] - mean);
        s2[tid] = q2raw;
    }
    __syncthreads();

    // ---- window stats: 4 windows/thread via sliding update ----
    {
        int p0 = tid * 4;
        float s = 0.f, qq = 0.f;
#pragma unroll
        for (int l = 0; l < 64; ++l) {
            float v = xr[p0 + l];
            s += v;
            qq = fmaf(v, v, qq);
        }
        p2c[p0] = (p0 < P_) ? fmaf(-s, s * (1.f / 64.f), qq) : 3.0e30f;
#pragma unroll
        for (int k = 1; k < 4; ++k) {
            float vo = xr[p0 + k - 1], vi = xr[p0 + 63 + k];
            s += vi - vo;
            qq += fmaf(vi, vi, -vo * vo);
            int p = p0 + k;
            p2c[p] = (p < P_) ? fmaf(-s, s * (1.f / 64.f), qq) : 3.0e30f;
        }
    }
    __syncthreads();

    // ---- persistent B fragments: 2 n-chunks x 8 k-chunks x 2 regs ----
    const int h = wid >> 3, q = wid & 7;
    const uint32_t* Bu = reinterpret_cast<const uint32_t*>(Bs);
    uint32_t Bf[2][8][2];
#pragma unroll
    for (int nc = 0; nc < 2; ++nc) {
        int row = q * 16 + nc * 8 + gid;
#pragma unroll
        for (int kc = 0; kc < 8; ++kc) {
            Bf[nc][kc][0] = Bu[row * BSTRIDE + kc * 8 + tig];
            Bf[nc][kc][1] = Bu[row * BSTRIDE + kc * 8 + tig + 4];
        }
    }

    float mn[4] = {3.4e38f, 3.4e38f, 3.4e38f, 3.4e38f};
    const uint32_t* xu = reinterpret_cast<const uint32_t*>(xr);
    const int mstart = h * 1024;

    // ---- main loop: 64 m-groups, software-pipelined, unrolled by 2 ----
    uint32_t va[18], vb[18];
    int rb = mstart + gid;
#pragma unroll
    for (int j = 0; j < 18; ++j) va[j] = xu[rb + tig + 4 * j];
    float pc0 = p2c[rb], pc1 = p2c[rb + 8];
    float npc0, npc1;

    for (int it = 0; it < 32; ++it) {
        // even group: consume va, prefetch into vb
        mg_step(va, vb, rb + 16 + tig, rb + 16, Bf, pc0, pc1, npc0, npc1,
                mn, xu, p2c);
        pc0 = npc0; pc1 = npc1;
        // odd group: consume vb, prefetch into va (last prefetch overruns
        // into padded xr / s2-wmin smem — in-bounds, values never used)
        mg_step(vb, va, rb + 32 + tig, rb + 32, Bf, pc0, pc1, npc0, npc1,
                mn, xu, p2c);
        pc0 = npc0; pc1 = npc1;
        rb += 32;
    }

    // ---- reduce over the 8 row-groups (lanes with same tig) ----
#pragma unroll
    for (int i = 0; i < 4; ++i) {
        int nc = i >> 1, e = i & 1;
        float m = mn[i];
        m = fminf(m, __shfl_xor_sync(0xffffffffu, m, 4));
        m = fminf(m, __shfl_xor_sync(0xffffffffu, m, 8));
        m = fminf(m, __shfl_xor_sync(0xffffffffu, m, 16));
        if (lane < 4)
            wmin[h * 128 + q * 16 + nc * 8 + lane * 2 + e] = m;
    }
    __syncthreads();

    // ---- combine m-halves, add s2, sqrt, store ----
    if (tid < S_) {
        float d2 = fminf(wmin[tid], wmin[128 + tid]) + s2[tid];
        out[(size_t)b * S_ + tid] = sqrtf(fmaxf(d2, 0.f));
    }
}

extern "C" void kernel_launch(void* const* d_in, const int* in_sizes, int n_in,
                              void* d_out, int out_size) {
    const float* x  = (const float*)d_in[0];   // (512, 1, 2048) fp32
    const float* sh = (const float*)d_in[1];   // (128, 1, 64)   fp32
    float* out = (float*)d_out;                // (512, 128)     fp32
    cudaFuncSetAttribute(shapelet_mma_kernel,
                         cudaFuncAttributeMaxDynamicSharedMemorySize, SMEM_BYTES);
    shapelet_mma_kernel<<<B_, THREADS, SMEM_BYTES>>>(x, sh, out);
}

// round 6
// speedup vs baseline: 1.7342x; 1.7342x over previous
#include <cuda_runtime.h>
#include <cstdint>

#define B_ 512
#define T_ 2048
#define S_ 128
#define P_ 1985
#define THREADS 512
#define BPSTRIDE 33   // u32 stride for packed shapelet rows (conflict spread)

// smem floats: xr[2176] | xpair[2176] | Bp[128*33] | p2c[2048] | s2[128] | wmin[256]
#define SMEM_FLOATS (2176 + 2176 + 128 * BPSTRIDE + 2048 + 128 + 256)
#define SMEM_BYTES  (SMEM_FLOATS * 4)

extern __shared__ float smf[];

static __device__ __forceinline__ uint32_t pack_bf16x2(float lo, float hi) {
    uint32_t r;  // d.hi = cvt(%1), d.lo = cvt(%2)
    asm("cvt.rn.bf16x2.f32 %0, %1, %2;" : "=r"(r) : "f"(hi), "f"(lo));
    return r;
}

// bf16 m16n8k16: D = A*B + 0
static __device__ __forceinline__ void mma16_zc(float d[4],
        uint32_t a0, uint32_t a1, uint32_t a2, uint32_t a3,
        uint32_t b0, uint32_t b1) {
    asm volatile(
        "mma.sync.aligned.m16n8k16.row.col.f32.bf16.bf16.f32 "
        "{%0,%1,%2,%3}, {%4,%5,%6,%7}, {%8,%9}, {%10,%10,%10,%10};"
        : "=f"(d[0]), "=f"(d[1]), "=f"(d[2]), "=f"(d[3])
        : "r"(a0), "r"(a1), "r"(a2), "r"(a3), "r"(b0), "r"(b1), "f"(0.f));
}
// bf16 m16n8k16: D = A*B + D
static __device__ __forceinline__ void mma16_acc(float d[4],
        uint32_t a0, uint32_t a1, uint32_t a2, uint32_t a3,
        uint32_t b0, uint32_t b1) {
    asm volatile(
        "mma.sync.aligned.m16n8k16.row.col.f32.bf16.bf16.f32 "
        "{%0,%1,%2,%3}, {%4,%5,%6,%7}, {%8,%9}, {%0,%1,%2,%3};"
        : "+f"(d[0]), "+f"(d[1]), "+f"(d[2]), "+f"(d[3])
        : "r"(a0), "r"(a1), "r"(a2), "r"(a3), "r"(b0), "r"(b1));
}

// One CTA per batch sample; 16 warps = 2 m-halves x 8 column groups.
// Stats (p2c, s2) in exact fp32 from raw x; only the cross-term runs in bf16.
__global__ void __launch_bounds__(THREADS, 2)
shapelet_mma_kernel(const float* __restrict__ x,
                    const float* __restrict__ sh,
                    float* __restrict__ out) {
    float*    xr  = smf;                        // raw x row, zero-padded to 2176
    uint32_t* xp  = reinterpret_cast<uint32_t*>(smf + 2176);  // bf16 pairs (x[i],x[i+1])
    uint32_t* Bp  = reinterpret_cast<uint32_t*>(smf + 4352);  // centered shapelet bf16 pairs
    float*    p2c = smf + 4352 + 128 * BPSTRIDE;  // centered window sq-norm, 2048
    float*    s2  = p2c + 2048;                   // RAW shapelet sq-norm
    float*    wmin = s2 + 128;                    // per-half per-col mins, 2*128

    const int tid = threadIdx.x, b = blockIdx.x;
    const int wid = tid >> 5, lane = tid & 31;
    const int gid = lane >> 2, tig = lane & 3;

    // ---- raw x row ----
    const float* xg = x + (size_t)b * T_;
    for (int i = tid; i < 2176; i += THREADS)
        xr[i] = (i < T_) ? xg[i] : 0.f;
    __syncthreads();

    // ---- pack bf16 pairs of x ----
    for (int i = tid; i < 2176; i += THREADS) {
        float hi = (i + 1 < 2176) ? xr[i + 1] : 0.f;
        xp[i] = pack_bf16x2(xr[i], hi);
    }

    // ---- centered shapelets -> packed bf16 pairs; s2 = RAW squared norm ----
    if (tid < S_) {
        const float* sp = sh + tid * 64;
        float sm = 0.f, q2raw = 0.f;
#pragma unroll
        for (int l = 0; l < 64; ++l) {
            float v = sp[l];
            sm += v;
            q2raw = fmaf(v, v, q2raw);
        }
        float mean = sm * (1.f / 64.f);
#pragma unroll
        for (int l = 0; l < 32; ++l)
            Bp[tid * BPSTRIDE + l] =
                pack_bf16x2(sp[2 * l] - mean, sp[2 * l + 1] - mean);
        s2[tid] = q2raw;
    }

    // ---- window stats in exact fp32: 4 windows/thread, sliding update ----
    {
        int p0 = tid * 4;
        float s = 0.f, qq = 0.f;
#pragma unroll
        for (int l = 0; l < 64; ++l) {
            float v = xr[p0 + l];
            s += v;
            qq = fmaf(v, v, qq);
        }
        p2c[p0] = (p0 < P_) ? fmaf(-s, s * (1.f / 64.f), qq) : 3.0e30f;
#pragma unroll
        for (int k = 1; k < 4; ++k) {
            float vo = xr[p0 + k - 1], vi = xr[p0 + 63 + k];
            s += vi - vo;
            qq += fmaf(vi, vi, -vo * vo);
            int p = p0 + k;
            p2c[p] = (p < P_) ? fmaf(-s, s * (1.f / 64.f), qq) : 3.0e30f;
        }
    }
    __syncthreads();

    // ---- persistent B fragments: 2 n-chunks x 4 k16-chunks x 2 regs ----
    const int h = wid >> 3, q = wid & 7;
    uint32_t Bf[2][4][2];
#pragma unroll
    for (int nc = 0; nc < 2; ++nc) {
        int row = q * 16 + nc * 8 + gid;
#pragma unroll
        for (int kc = 0; kc < 4; ++kc) {
            Bf[nc][kc][0] = Bp[row * BPSTRIDE + tig + 8 * kc];       // k = 2t + 16kc
            Bf[nc][kc][1] = Bp[row * BPSTRIDE + tig + 4 + 8 * kc];   // k = 2t+8 + 16kc
        }
    }

    float mn[4] = {3.4e38f, 3.4e38f, 3.4e38f, 3.4e38f};
    const int mstart = h * 1024;

    // ---- main loop: 64 m-groups of 16 windows; 9 LDS + 8 MMAs each ----
    for (int mg = 0; mg < 64; ++mg) {
        const int rbase = mstart + mg * 16 + gid;
        // v[j] = xp[rbase + 2t + 8j]; fragments per kc:
        //   a0 = v[2kc]   (row g,   k=2t)      a1 = v[2kc+1] (row g+8, k=2t)
        //   a2 = v[2kc+1] (row g,   k=2t+8)    a3 = v[2kc+2] (row g+8, k=2t+8)
        uint32_t v[9];
#pragma unroll
        for (int j = 0; j < 9; ++j) v[j] = xp[rbase + 2 * tig + 8 * j];
        const float pc0 = p2c[rbase], pc1 = p2c[rbase + 8];

        float A0[4], A1[4];
        mma16_zc(A0, v[0], v[1], v[1], v[2], Bf[0][0][0], Bf[0][0][1]);
        mma16_zc(A1, v[0], v[1], v[1], v[2], Bf[1][0][0], Bf[1][0][1]);
#pragma unroll
        for (int kc = 1; kc < 4; ++kc) {
            mma16_acc(A0, v[2 * kc], v[2 * kc + 1], v[2 * kc + 1], v[2 * kc + 2],
                      Bf[0][kc][0], Bf[0][kc][1]);
            mma16_acc(A1, v[2 * kc], v[2 * kc + 1], v[2 * kc + 1], v[2 * kc + 2],
                      Bf[1][kc][0], Bf[1][kc][1]);
        }
        mn[0] = fminf(mn[0], fminf(fmaf(A0[0], -2.f, pc0), fmaf(A0[2], -2.f, pc1)));
        mn[1] = fminf(mn[1], fminf(fmaf(A0[1], -2.f, pc0), fmaf(A0[3], -2.f, pc1)));
        mn[2] = fminf(mn[2], fminf(fmaf(A1[0], -2.f, pc0), fmaf(A1[2], -2.f, pc1)));
        mn[3] = fminf(mn[3], fminf(fmaf(A1[1], -2.f, pc0), fmaf(A1[3], -2.f, pc1)));
    }

    // ---- reduce over the 8 row-groups (lanes sharing tig) ----
#pragma unroll
    for (int i = 0; i < 4; ++i) {
        int nc = i >> 1, e = i & 1;
        float m = mn[i];
        m = fminf(m, __shfl_xor_sync(0xffffffffu, m, 4));
        m = fminf(m, __shfl_xor_sync(0xffffffffu, m, 8));
        m = fminf(m, __shfl_xor_sync(0xffffffffu, m, 16));
        if (lane < 4)
            wmin[h * 128 + q * 16 + nc * 8 + lane * 2 + e] = m;
    }
    __syncthreads();

    // ---- combine m-halves, add s2, sqrt, store ----
    if (tid < S_) {
        float d2 = fminf(wmin[tid], wmin[128 + tid]) + s2[tid];
        out[(size_t)b * S_ + tid] = sqrtf(fmaxf(d2, 0.f));
    }
}

extern "C" void kernel_launch(void* const* d_in, const int* in_sizes, int n_in,
                              void* d_out, int out_size) {
    const float* x  = (const float*)d_in[0];   // (512, 1, 2048) fp32
    const float* sh = (const float*)d_in[1];   // (128, 1, 64)   fp32
    float* out = (float*)d_out;                // (512, 128)     fp32
    cudaFuncSetAttribute(shapelet_mma_kernel,
                         cudaFuncAttributeMaxDynamicSharedMemorySize, SMEM_BYTES);
    shapelet_mma_kernel<<<B_, THREADS, SMEM_BYTES>>>(x, sh, out);
}